// round 17
// baseline (speedup 1.0000x reference)
#include <cuda_runtime.h>
#include <cstdint>
#include <math.h>

#define DD   512
#define NPOS 128
#define NB   32
#define LUT  256

// ---------------- device scratch ----------------
__device__ float g_G[DD * DD];                 // G = I - P P^T
__device__ float g_A[NPOS][DD * DD];           // per-step working matrices
__device__ float g_piv[NPOS][DD];              // pivots u_jj per step
__device__ int   g_posrank[DD];
__device__ float g_picked[NPOS];

// smem layout (floats):
//   stage: 2 x 128*128          at 0       (131072 B)
//   sm:    512*33               at 32768   (67584 B)
//   smd:   32*33                at 49664
//   sinv:  32                   at 50720
// total 50752 floats = 203008 B
#define STAGE_OFF 0
#define SM_OFF    32768
#define SMD_OFF   49664
#define SINV_OFF  50720
#define SMEM_FLOATS 50752

__device__ __forceinline__ unsigned int smem_u32(const void* p) {
    unsigned int a;
    asm("{ .reg .u64 t; cvta.to.shared.u64 t, %1; cvt.u32.u64 %0, t; }" : "=r"(a) : "l"(p));
    return a;
}
__device__ __forceinline__ void cp16(unsigned int dst, const float* src) {
    asm volatile("cp.async.cg.shared.global [%0], [%1], 16;" :: "r"(dst), "l"(src));
}

// ---------------- kernel 0 ----------------
__global__ void posrank_kernel(const int* __restrict__ pos) {
    int t = threadIdx.x;
    if (t < DD) g_posrank[t] = 0x7fffffff;
    __syncthreads();
    if (t < NPOS) g_posrank[pos[t]] = t;
}

// ---------------- kernel 1: G = I - P P^T ----------------
__global__ void gmat_kernel(const float* __restrict__ P) {
    __shared__ float sA[16][NPOS + 1];
    __shared__ float sB[16][NPOS + 1];
    int tx = threadIdx.x, ty = threadIdx.y;
    int tid = ty * 16 + tx;
    int i0 = blockIdx.y * 16, j0 = blockIdx.x * 16;

    for (int t = tid; t < 16 * NPOS; t += 256) {
        int r = t >> 7, c = t & (NPOS - 1);
        sA[r][c] = P[(i0 + r) * NPOS + c];
        sB[r][c] = P[(j0 + r) * NPOS + c];
    }
    __syncthreads();

    float acc = 0.0f;
#pragma unroll 8
    for (int c = 0; c < NPOS; c++) acc += sA[ty][c] * sB[tx][c];

    int i = i0 + ty, j = j0 + tx;
    g_G[i * DD + j] = ((i == j) ? 1.0f : 0.0f) - acc;
}

// ---------------- kernel 2: A_k = G - diag(occ_prefix_k) ----------------
__global__ void init_kernel() {
    int k = blockIdx.y;
    int n = DD - NPOS + k + 1;
    int r0 = blockIdx.x * 32;
    for (int r = r0; r < r0 + 32 && r < n; r++) {
        int dec = (g_posrank[r] < k) ? 1 : 0;
        float* dst = g_A[k] + (size_t)r * DD;
        const float* src = g_G + (size_t)r * DD;
        for (int j = threadIdx.x; j < n; j += blockDim.x) {
            float v = src[j];
            if (j == r && dec) v -= 1.0f;
            dst[j] = v;
        }
    }
}

// ---------------- kernel 3: blocked elimination, one CTA per k ----------------
// R13 structure with ONE coherent change in the trailing update:
//  - sl panel removed (L recomputed as M*sinv on the fly — bitwise identical)
//  - acc tiles double-buffered through smem via cp.async: prefetch tile idx+1
//    while computing tile idx out of smem (LDS) instead of long-latency LDG.
__global__ void lu_kernel() {
    int k = blockIdx.x;
    int n = DD - NPOS + k + 1;
    float* A = g_A[k];
    extern __shared__ float smem[];
    float* stage = smem + STAGE_OFF;        // 2 x [128][128]
    float* sm    = smem + SM_OFF;           // [512][33] M panel (= L*d)
    float* smd   = smem + SMD_OFF;          // [32][33] diag-block U rows
    float* sinv  = smem + SINV_OFF;         // [32] 1/d
    const int tid = threadIdx.x;
    const unsigned int stage_b = smem_u32(stage);

    for (int p = 0; p < n; p += NB) {
        int pw   = min(NB, n - p);
        int rows = n - p;

        // load panel (coalesced: 32 consecutive floats per row)
        for (int t = tid; t < rows * NB; t += LUT) {
            int r = t >> 5, c = t & 31;
            float v = (c < pw) ? A[(size_t)(p + r) * DD + (p + c)] : 0.0f;
            sm[r * 33 + c] = v;
        }
        __syncthreads();

        // ---- phase 1: warp 0 factors the 32x32 diag block (warp-sync, shfl) ----
        if (tid < 32) {
            int r = tid;
            float a[NB];
#pragma unroll
            for (int c = 0; c < NB; c++)
                a[c] = (r < rows) ? sm[r * 33 + c] : ((r == c) ? 1.0f : 0.0f);
#pragma unroll
            for (int c = 0; c < NB; c++) {
                float d = __shfl_sync(0xffffffffu, a[c], c);
                float inv = 1.0f / d;
                if (r == c) {
#pragma unroll
                    for (int j = 0; j < NB; j++) smd[c * 33 + j] = a[j];
                    sinv[c] = inv;
                }
                float l = a[c] * inv;
#pragma unroll
                for (int j = c + 1; j < NB; j++) {
                    float uc = __shfl_sync(0xffffffffu, a[j], c);
                    if (r > c) a[j] -= l * uc;
                }
            }
            if (r < pw) g_piv[k][p + r] = a[r];
        }
        __syncthreads();

        // ---- phase 2: row-parallel M strip (L kept in regs only) ----
        for (int i = NB + tid; i < rows; i += LUT) {
            float l[NB];
#pragma unroll
            for (int c = 0; c < NB; c++) {
                float m = sm[i * 33 + c];
#pragma unroll
                for (int t2 = 0; t2 < NB; t2++)
                    if (t2 < c) m -= l[t2] * smd[t2 * 33 + c];
                float lv = m * sinv[c];
                l[c] = lv;
                sm[i * 33 + c] = m;    // M = L*d
            }
        }
        __syncthreads();

        // ---- trailing symmetric rank-pw update: LOWER tiles, cp.async pipelined ----
        int tr0 = p + pw;
        int tsz = n - tr0;
        if (tsz > 0) {
            int tx = tid & 15, ty = tid >> 4;   // 16x16 thread grid
            int nt = (tsz + 127) >> 7;
            int np2 = (nt * (nt + 1)) >> 1;

            const int cr = tid >> 1;            // copy row 0..127
            const int ch = tid & 1;             // half of 512B row

            // prefetch pair 0 into buffer 0
            {
                int gr = tr0 + cr; if (gr > DD - 1) gr = DD - 1;
                const float* srow = A + (size_t)gr * DD;
                int cb = tr0 + ch * 64;
                unsigned int d = stage_b + (unsigned int)(cr * 128 + ch * 64) * 4u;
#pragma unroll
                for (int m = 0; m < 16; m++) {
                    int gc = cb + m * 4;
                    const float* s = (gc + 4 <= DD) ? (srow + gc) : srow;
                    cp16(d + m * 16, s);
                }
                asm volatile("cp.async.commit_group;");
            }

            int buf = 0;
            for (int idx = 0; idx < np2; idx++) {
                // decode current pair
                int bi = 0;
                while ((((bi + 1) * (bi + 2)) >> 1) <= idx) bi++;
                int bj = idx - ((bi * (bi + 1)) >> 1);
                int i0 = bi << 7, j0 = bj << 7;

                if (idx + 1 < np2) {
                    // prefetch next pair into other buffer
                    int bi2 = bi, idx2 = idx + 1;
                    while ((((bi2 + 1) * (bi2 + 2)) >> 1) <= idx2) bi2++;
                    int bj2 = idx2 - ((bi2 * (bi2 + 1)) >> 1);
                    int i02 = bi2 << 7, j02 = bj2 << 7;
                    int gr = tr0 + i02 + cr; if (gr > DD - 1) gr = DD - 1;
                    const float* srow = A + (size_t)gr * DD;
                    int cb = tr0 + j02 + ch * 64;
                    unsigned int d = stage_b + (unsigned int)((buf ^ 1) * 16384 + cr * 128 + ch * 64) * 4u;
#pragma unroll
                    for (int m = 0; m < 16; m++) {
                        int gc = cb + m * 4;
                        const float* s = (gc + 4 <= DD) ? (srow + gc) : srow;
                        cp16(d + m * 16, s);
                    }
                    asm volatile("cp.async.commit_group;");
                    asm volatile("cp.async.wait_group 1;");
                } else {
                    asm volatile("cp.async.wait_group 0;");
                }
                __syncthreads();   // all threads' copies for buffer `buf` complete

                int iidx[8], jidx[8];
                bool iv[8], jv[8];
#pragma unroll
                for (int u = 0; u < 8; u++) {
                    int il = i0 + ty + 16 * u;
                    iv[u] = (il < tsz); iidx[u] = iv[u] ? il : 0;
                }
#pragma unroll
                for (int v = 0; v < 8; v++) {
                    int jl = j0 + tx + 16 * v;
                    jv[v] = (jl < tsz); jidx[v] = jv[v] ? jl : 0;
                }

                const float* stg = stage + buf * 16384;
                float acc[8][8];
#pragma unroll
                for (int u = 0; u < 8; u++)
#pragma unroll
                    for (int v = 0; v < 8; v++)
                        acc[u][v] = (iv[u] && jv[v])
                            ? stg[(ty + 16 * u) * 128 + tx + 16 * v] : 0.0f;

                for (int c = 0; c < pw; c++) {
                    float s = sinv[c];
                    float Ls[8], Mr[8];
#pragma unroll
                    for (int u = 0; u < 8; u++) Ls[u] = sm[(pw + iidx[u]) * 33 + c] * s;
#pragma unroll
                    for (int v = 0; v < 8; v++) Mr[v] = sm[(pw + jidx[v]) * 33 + c];
#pragma unroll
                    for (int u = 0; u < 8; u++)
#pragma unroll
                        for (int v = 0; v < 8; v++)
                            acc[u][v] -= Ls[u] * Mr[v];
                }
#pragma unroll
                for (int u = 0; u < 8; u++)
#pragma unroll
                    for (int v = 0; v < 8; v++)
                        if (iv[u] && jv[v])
                            A[(size_t)(tr0 + iidx[u]) * DD + tr0 + jidx[v]] = acc[u][v];

                __syncthreads();   // buffer consumed; safe to overwrite next iter
                buf ^= 1;
            }

            // corner fix: 31-wide upper band crossing 128-tile boundaries lies in
            // skipped strictly-upper tiles — update those elements explicitly.
            for (int bt = 1; bt * 128 < tsz; bt++) {
                int base = bt << 7;
                for (int t = tid; t < 32 * 32; t += LUT) {
                    int x = t >> 5, y = t & 31;
                    int rl = base - 32 + x, cl = base + y;
                    if (y < x && cl < tsz) {
                        float a = A[(size_t)(tr0 + rl) * DD + tr0 + cl];
#pragma unroll
                        for (int c = 0; c < NB; c++)
                            a -= (sm[(pw + rl) * 33 + c] * sinv[c]) * sm[(pw + cl) * 33 + c];
                        A[(size_t)(tr0 + rl) * DD + tr0 + cl] = a;
                    }
                }
            }
        }
        __syncthreads();
    }
}

// ---------------- kernel 4: probs rows via smem-staged sequential cumprod ----------------
__global__ void probs_kernel(const int* __restrict__ pos, float* __restrict__ out) {
    int k = blockIdx.x;
    __shared__ float sp[DD];
    __shared__ float srow[DD];
    float* row = out + (size_t)k * DD;
    for (int i = threadIdx.x; i < DD; i += blockDim.x) {
        sp[i] = g_piv[k][i];
        srow[i] = 0.0f;
    }
    __syncthreads();
    if (threadIdx.x == 0) {
        int xmin = (k == 0) ? 0 : (pos[k - 1] + 1);
        int xmax = DD - NPOS + k + 1;
        int pk = pos[k];
        float c = 1.0f, picked = 0.0f;
        for (int i = xmin; i < xmax; i++) {
            float u = sp[i];
            float pr = c * (1.0f - u);
            pr = (fabsf(pr) > 1e-15f) ? pr : 0.0f;
            srow[i] = pr;
            if (i == pk) picked = pr;
            c *= u;
        }
        g_picked[k] = logf(picked);
    }
    __syncthreads();
    for (int i = threadIdx.x; i < DD; i += blockDim.x) row[i] = srow[i];
}

// ---------------- kernel 5: deterministic log-sum ----------------
__global__ void finalize_kernel(float* __restrict__ out, int out_size) {
    __shared__ float s[NPOS];
    if (threadIdx.x < NPOS) s[threadIdx.x] = g_picked[threadIdx.x];
    __syncthreads();
    if (threadIdx.x == 0) {
        float t = 0.0f;
        for (int i = 0; i < NPOS; i++) t += s[i];
        out[out_size - 1] = t;
    }
}

// ---------------- launch ----------------
extern "C" void kernel_launch(void* const* d_in, const int* in_sizes, int n_in,
                              void* d_out, int out_size) {
    const float* P   = (const float*)d_in[0];
    const int*   pos = (const int*)d_in[1];
    float*       out = (float*)d_out;

    size_t lu_smem = (size_t)SMEM_FLOATS * sizeof(float);   // 203008 B
    cudaFuncSetAttribute(lu_kernel, cudaFuncAttributeMaxDynamicSharedMemorySize, (int)lu_smem);

    posrank_kernel<<<1, 512>>>(pos);
    gmat_kernel<<<dim3(DD / 16, DD / 16), dim3(16, 16)>>>(P);
    init_kernel<<<dim3(16, NPOS), 256>>>();
    lu_kernel<<<NPOS, LUT, lu_smem>>>();
    probs_kernel<<<NPOS, 256>>>(pos, out);
    finalize_kernel<<<1, 128>>>(out, out_size);
}